// round 2
// baseline (speedup 1.0000x reference)
#include <cuda_runtime.h>
#include <cuda_bf16.h>
#include <math.h>

#define B_  32
#define S_  1024
#define E_  64
#define H_  4
#define HD_ 16
#define HID_ 256
#define AD_ 32
#define NS_ 64
#define NT_ (B_*S_)   // 32768 tokens

// ---------------- scratch (no allocations allowed) ----------------
__device__ float g_q[B_*H_*S_*HD_];
__device__ float g_k[B_*H_*S_*HD_];
__device__ float g_v[B_*H_*S_*HD_];
__device__ float g_o[B_*S_*E_];

// ======================= kernel 1: rmsnorm + QKV =======================
// warp-per-token; wq/wk/wv transposed in smem with pad-65 rows.
__global__ void __launch_bounds__(256) qkv_kernel(
    const float* __restrict__ x, const float* __restrict__ nw,
    const float* __restrict__ wq, const float* __restrict__ wk,
    const float* __restrict__ wv)
{
    extern __shared__ float sm[];
    float* wT   = sm;               // 3 * 64*65 = 12480
    float* nws  = wT + 3*4160;      // 64
    float* rows = nws + 64;         // 8 * 64

    const int tid  = threadIdx.x;
    const int lane = tid & 31;
    const int w    = tid >> 5;

    for (int i = tid; i < 64*64; i += blockDim.x) {
        int e = i >> 6, j = i & 63;
        wT[0*4160 + j*65 + e] = wq[i];
        wT[1*4160 + j*65 + e] = wk[i];
        wT[2*4160 + j*65 + e] = wv[i];
    }
    if (tid < 64) nws[tid] = nw[tid];
    __syncthreads();

    float* hrow = rows + w*64;

    for (int tok = blockIdx.x*8 + w; tok < NT_; tok += gridDim.x*8) {
        const int b = tok >> 10, s = tok & 1023;
        float x0 = x[tok*64 + lane];
        float x1 = x[tok*64 + lane + 32];
        float ss = x0*x0 + x1*x1;
        #pragma unroll
        for (int o = 16; o; o >>= 1) ss += __shfl_xor_sync(~0u, ss, o);
        float rinv = rsqrtf(ss * (1.f/64.f) + 1e-5f);
        hrow[lane]      = x0 * rinv * nws[lane];
        hrow[lane + 32] = x1 * rinv * nws[lane + 32];
        __syncwarp();

        #pragma unroll
        for (int p = 0; p < 3; p++) {
            const float* wp = wT + p*4160;
            float* dst = (p == 0) ? g_q : (p == 1 ? g_k : g_v);
            #pragma unroll
            for (int r = 0; r < 2; r++) {
                int e = lane + r*32;
                float acc = 0.f;
                #pragma unroll
                for (int j = 0; j < 64; j++) acc += hrow[j] * wp[j*65 + e];
                int hh = e >> 4, d = e & 15;
                dst[(((b*H_ + hh)*S_) + s)*HD_ + d] = acc;
            }
        }
        __syncwarp();
    }
}

// ======================= kernel 2: causal attention =======================
// 256 blocks: idx<128 -> heavy half (queries 512..1023, 1024 keys in smem),
// idx>=128 -> light half (queries 0..511, 512 keys). Thread = one query.
__global__ void __launch_bounds__(512, 1) attn_kernel()
{
    const int bi   = blockIdx.x;
    const int half = (bi < 128) ? 1 : 0;
    const int bh   = half ? bi : bi - 128;
    const int nk   = (half + 1) * 512;

    extern __shared__ float sm[];
    float* Ks = sm;            // 1024*16 slot
    float* Vs = sm + 16384;

    const float* kg = g_k + bh * S_ * HD_;
    const float* vg = g_v + bh * S_ * HD_;
    for (int i = threadIdx.x; i < nk*16; i += 512) { Ks[i] = kg[i]; Vs[i] = vg[i]; }
    __syncthreads();

    const int q = half*512 + threadIdx.x;
    const float* qp = g_q + (bh*S_ + q) * HD_;
    float qr[16];
    #pragma unroll
    for (int d = 0; d < 16; d++) qr[d] = qp[d] * 0.25f;   // fold 1/sqrt(HD)

    float m = -1e30f, l = 0.f;
    float acc[16];
    #pragma unroll
    for (int d = 0; d < 16; d++) acc[d] = 0.f;

    const int jmax = q | 31;   // warp-uniform upper bound
    for (int j = 0; j <= jmax; j++) {
        const float4* kr = (const float4*)(Ks + j*16);
        float4 k0 = kr[0], k1 = kr[1], k2 = kr[2], k3 = kr[3];
        float s = qr[0]*k0.x + qr[1]*k0.y + qr[2]*k0.z + qr[3]*k0.w
                + qr[4]*k1.x + qr[5]*k1.y + qr[6]*k1.z + qr[7]*k1.w
                + qr[8]*k2.x + qr[9]*k2.y + qr[10]*k2.z + qr[11]*k2.w
                + qr[12]*k3.x + qr[13]*k3.y + qr[14]*k3.z + qr[15]*k3.w;
        if (j <= q) {
            if (s > m) {   // rare after warmup -> avoids per-step acc rescale
                float c = __expf(m - s);
                l *= c;
                #pragma unroll
                for (int d = 0; d < 16; d++) acc[d] *= c;
                m = s;
            }
            float p = __expf(s - m);
            l += p;
            const float4* vr = (const float4*)(Vs + j*16);
            float4 v0 = vr[0], v1 = vr[1], v2 = vr[2], v3 = vr[3];
            acc[0]  += p*v0.x; acc[1]  += p*v0.y; acc[2]  += p*v0.z; acc[3]  += p*v0.w;
            acc[4]  += p*v1.x; acc[5]  += p*v1.y; acc[6]  += p*v1.z; acc[7]  += p*v1.w;
            acc[8]  += p*v2.x; acc[9]  += p*v2.y; acc[10] += p*v2.z; acc[11] += p*v2.w;
            acc[12] += p*v3.x; acc[13] += p*v3.y; acc[14] += p*v3.z; acc[15] += p*v3.w;
        }
    }
    const float inv = 1.f / l;
    const int b = bh >> 2, h = bh & 3;
    float* op = g_o + (b*S_ + q)*E_ + h*16;
    #pragma unroll
    for (int d = 0; d < 16; d++) op[d] = acc[d] * inv;
}

// ======================= kernel 3: wo-proj + residual + memory read =======================
__global__ void __launch_bounds__(256) mem_kernel(
    const float* __restrict__ x,     const float* __restrict__ mvals,
    const float* __restrict__ maddr, const float* __restrict__ mnw,
    const float* __restrict__ wo,    const float* __restrict__ mq,
    const float* __restrict__ mo,    float* __restrict__ out)
{
    extern __shared__ float sm[];
    float* woT  = sm;              // 64*65
    float* moT  = woT + 4160;      // 64*65
    float* mqT  = moT + 4160;      // 64*33
    float* aT   = mqT + 2112;      // 32*65
    float* mnws = aT + 2080;       // 64
    float* rows = mnws + 64;       // 8 * 96

    const int tid = threadIdx.x, lane = tid & 31, w = tid >> 5;

    for (int i = tid; i < 4096; i += blockDim.x) {
        int e = i >> 6, j = i & 63;
        woT[j*65 + e] = wo[i];
        moT[j*65 + e] = mo[i];
    }
    for (int i = tid; i < AD_*E_; i += blockDim.x) {
        int a = i >> 6, e = i & 63;
        mqT[e*33 + a] = mq[i];
    }
    if (tid < 64) mnws[tid] = mnw[tid];
    if (tid < 64) {
        float ssum = 0.f, v[32];
        #pragma unroll
        for (int a = 0; a < 32; a++) { v[a] = maddr[tid*32 + a]; ssum += v[a]*v[a]; }
        float rn = 1.f / fmaxf(sqrtf(ssum), 1e-12f);
        #pragma unroll
        for (int a = 0; a < 32; a++) aT[a*65 + tid] = v[a] * rn;
    }
    __syncthreads();

    float* hrow = rows + w*96;
    float* qrow = hrow + 64;

    for (int tok = blockIdx.x*8 + w; tok < NT_; tok += gridDim.x*8) {
        const int b = tok >> 10;
        // attention output row into smem for the WO dot
        hrow[lane]      = g_o[tok*64 + lane];
        hrow[lane + 32] = g_o[tok*64 + lane + 32];
        __syncwarp();
        float x1a = x[tok*64 + lane], x1b = x[tok*64 + lane + 32];
        {
            float s0 = 0.f, s1 = 0.f;
            #pragma unroll
            for (int j = 0; j < 64; j++) {
                float hv = hrow[j];
                s0 += hv * woT[j*65 + lane];
                s1 += hv * woT[j*65 + lane + 32];
            }
            x1a += s0; x1b += s1;
        }
        __syncwarp();
        // rmsnorm
        float ss = x1a*x1a + x1b*x1b;
        #pragma unroll
        for (int o = 16; o; o >>= 1) ss += __shfl_xor_sync(~0u, ss, o);
        float rinv = rsqrtf(ss * (1.f/64.f) + 1e-5f);
        hrow[lane]      = x1a * rinv * mnws[lane];
        hrow[lane + 32] = x1b * rinv * mnws[lane + 32];
        __syncwarp();
        // memory query (one output per lane), then l2norm
        float qa = 0.f;
        #pragma unroll
        for (int e = 0; e < 64; e++) qa += hrow[e] * mqT[e*33 + lane];
        float qs = qa*qa;
        #pragma unroll
        for (int o = 16; o; o >>= 1) qs += __shfl_xor_sync(~0u, qs, o);
        float rq = 1.f / fmaxf(sqrtf(qs), 1e-12f);
        qrow[lane] = qa * rq;
        __syncwarp();
        // 64 scores, 2 per lane (scale by 1/TEMP = 4)
        float sc0 = 0.f, sc1 = 0.f;
        #pragma unroll
        for (int a = 0; a < 32; a++) {
            float qv = qrow[a];
            sc0 += qv * aT[a*65 + lane];
            sc1 += qv * aT[a*65 + lane + 32];
        }
        sc0 *= 4.f; sc1 *= 4.f;
        // iterative top-8 (tie -> lower index, matching lax.top_k)
        float tv[8]; int ti[8];
        float c0 = sc0, c1 = sc1; int i0 = lane, i1 = lane + 32;
        #pragma unroll
        for (int k = 0; k < 8; k++) {
            float bv; int bidx;
            if (c0 > c1 || (c0 == c1 && i0 < i1)) { bv = c0; bidx = i0; }
            else                                   { bv = c1; bidx = i1; }
            #pragma unroll
            for (int o = 16; o; o >>= 1) {
                float ov = __shfl_xor_sync(~0u, bv, o);
                int   oi = __shfl_xor_sync(~0u, bidx, o);
                if (ov > bv || (ov == bv && oi < bidx)) { bv = ov; bidx = oi; }
            }
            tv[k] = bv; ti[k] = bidx;
            if (bidx == i0) c0 = -1e30f;
            if (bidx == i1) c1 = -1e30f;
        }
        // softmax over top-8 (tv[0] is the max)
        float wsum = 0.f, wk8[8];
        #pragma unroll
        for (int k = 0; k < 8; k++) { wk8[k] = __expf(tv[k] - tv[0]); wsum += wk8[k]; }
        float winv = 1.f / wsum;
        // weighted gather of memory values
        const float* mb = mvals + b * NS_ * E_;
        float r0 = 0.f, r1 = 0.f;
        #pragma unroll
        for (int k = 0; k < 8; k++) {
            float wv = wk8[k] * winv;
            const float* mrow = mb + ti[k]*64;
            r0 += wv * mrow[lane];
            r1 += wv * mrow[lane + 32];
        }
        hrow[lane] = r0; hrow[lane + 32] = r1;
        __syncwarp();
        // mem_out projection + residual
        float o0 = 0.f, o1 = 0.f;
        #pragma unroll
        for (int j = 0; j < 64; j++) {
            float rv = hrow[j];
            o0 += rv * moT[j*65 + lane];
            o1 += rv * moT[j*65 + lane + 32];
        }
        out[tok*64 + lane]      = x1a + o0;
        out[tok*64 + lane + 32] = x1b + o1;
        __syncwarp();
    }
}

// ======================= kernel 4: FFN (in-place on d_out) =======================
__global__ void __launch_bounds__(512) ffn_kernel(
    const float* __restrict__ fnw, const float* __restrict__ w1,
    const float* __restrict__ b1,  const float* __restrict__ w2,
    const float* __restrict__ b2,  float* __restrict__ out)
{
    extern __shared__ float sm[];
    float* w1T  = sm;              // 64*256
    float* w2T  = w1T + 16384;     // 256*64
    float* b1s  = w2T + 16384;     // 256
    float* b2s  = b1s + 256;       // 64
    float* fns  = b2s + 64;        // 64
    float* rows = fns + 64;        // 16 * 320

    const int tid = threadIdx.x, lane = tid & 31, w = tid >> 5;
    const int NW = blockDim.x >> 5;

    for (int i = tid; i < HID_*E_; i += blockDim.x) {
        int o = i >> 6, j = i & 63;
        w1T[j*256 + o] = w1[i];
    }
    for (int i = tid; i < E_*HID_; i += blockDim.x) {
        int e = i >> 8, j = i & 255;
        w2T[j*64 + e] = w2[i];
    }
    if (tid < 256) b1s[tid] = b1[tid];
    if (tid < 64) { b2s[tid] = b2[tid]; fns[tid] = fnw[tid]; }
    __syncthreads();

    float* hrow   = rows + w*320;
    float* hidrow = hrow + 64;

    for (int tok = blockIdx.x*NW + w; tok < NT_; tok += gridDim.x*NW) {
        float xa = out[tok*64 + lane], xb = out[tok*64 + lane + 32];
        float ss = xa*xa + xb*xb;
        #pragma unroll
        for (int o = 16; o; o >>= 1) ss += __shfl_xor_sync(~0u, ss, o);
        float rinv = rsqrtf(ss * (1.f/64.f) + 1e-5f);
        hrow[lane]      = xa * rinv * fns[lane];
        hrow[lane + 32] = xb * rinv * fns[lane + 32];
        __syncwarp();

        #pragma unroll
        for (int r = 0; r < 8; r++) {
            int o = lane + r*32;
            float acc = b1s[o];
            #pragma unroll
            for (int j = 0; j < 64; j++) acc += hrow[j] * w1T[j*256 + o];
            // exact GELU
            hidrow[o] = 0.5f * acc * (1.f + erff(acc * 0.70710678118654752f));
        }
        __syncwarp();

        float o0 = b2s[lane], o1 = b2s[lane + 32];
        #pragma unroll 16
        for (int j = 0; j < 256; j++) {
            float hv = hidrow[j];
            o0 += hv * w2T[j*64 + lane];
            o1 += hv * w2T[j*64 + lane + 32];
        }
        out[tok*64 + lane]      = xa + o0;
        out[tok*64 + lane + 32] = xb + o1;
        __syncwarp();
    }
}

// ======================= launch =======================
extern "C" void kernel_launch(void* const* d_in, const int* in_sizes, int n_in,
                              void* d_out, int out_size)
{
    const float* x     = (const float*)d_in[0];
    const float* maddr = (const float*)d_in[1];
    const float* mvals = (const float*)d_in[2];
    const float* anw   = (const float*)d_in[3];
    const float* wq    = (const float*)d_in[4];
    const float* wk    = (const float*)d_in[5];
    const float* wv    = (const float*)d_in[6];
    const float* wo    = (const float*)d_in[7];
    const float* mnw   = (const float*)d_in[8];
    const float* mq    = (const float*)d_in[9];
    const float* mo    = (const float*)d_in[10];
    const float* fnw   = (const float*)d_in[11];
    const float* w1    = (const float*)d_in[12];
    const float* b1    = (const float*)d_in[13];
    const float* w2    = (const float*)d_in[14];
    const float* b2    = (const float*)d_in[15];
    float* out = (float*)d_out;

    int sms = 148;
    cudaDeviceGetAttribute(&sms, cudaDevAttrMultiProcessorCount, 0);

    const int QKV_SMEM = (3*4160 + 64 + 8*64) * 4;       // 52,224 B
    const int ATT_SMEM = 32768 * 4;                      // 131,072 B
    const int MEM_SMEM = (4160*2 + 2112 + 2080 + 64 + 8*96) * 4;  // 53,376 B
    const int FFN_SMEM = (16384*2 + 256 + 64 + 64 + 16*320) * 4;  // 153,088 B

    cudaFuncSetAttribute(qkv_kernel, cudaFuncAttributeMaxDynamicSharedMemorySize, QKV_SMEM);
    cudaFuncSetAttribute(attn_kernel, cudaFuncAttributeMaxDynamicSharedMemorySize, ATT_SMEM);
    cudaFuncSetAttribute(mem_kernel, cudaFuncAttributeMaxDynamicSharedMemorySize, MEM_SMEM);
    cudaFuncSetAttribute(ffn_kernel, cudaFuncAttributeMaxDynamicSharedMemorySize, FFN_SMEM);

    qkv_kernel<<<512, 256, QKV_SMEM>>>(x, anw, wq, wk, wv);
    attn_kernel<<<256, 512, ATT_SMEM>>>();
    mem_kernel<<<512, 256, MEM_SMEM>>>(x, mvals, maddr, mnw, wo, mq, mo, out);
    ffn_kernel<<<sms, 512, FFN_SMEM>>>(fnw, w1, b1, w2, b2, out);
}

// round 3
// speedup vs baseline: 1.4505x; 1.4505x over previous
#include <cuda_runtime.h>
#include <cuda_bf16.h>
#include <math.h>

#define B_  32
#define S_  1024
#define E_  64
#define H_  4
#define HD_ 16
#define HID_ 256
#define AD_ 32
#define NS_ 64
#define NT_ (B_*S_)   // 32768 tokens

// ---------------- scratch (no allocations allowed) ----------------
__device__ float g_q[B_*H_*S_*HD_];
__device__ float g_k[B_*H_*S_*HD_];
__device__ float g_v[B_*H_*S_*HD_];
__device__ float g_o[B_*S_*E_];

// ---------------- packed f32x2 helpers ----------------
__device__ __forceinline__ unsigned long long pk2(float lo, float hi) {
    unsigned long long r;
    asm("mov.b64 %0,{%1,%2};" : "=l"(r) : "f"(lo), "f"(hi));
    return r;
}
__device__ __forceinline__ float2 upk2(unsigned long long v) {
    float2 f;
    asm("mov.b64 {%0,%1},%2;" : "=f"(f.x), "=f"(f.y) : "l"(v));
    return f;
}
__device__ __forceinline__ unsigned long long ffma2_(unsigned long long a,
                                                     unsigned long long b,
                                                     unsigned long long c) {
    unsigned long long d;
    asm("fma.rn.f32x2 %0,%1,%2,%3;" : "=l"(d) : "l"(a), "l"(b), "l"(c));
    return d;
}
__device__ __forceinline__ unsigned long long fmul2_(unsigned long long a,
                                                     unsigned long long b) {
    unsigned long long d;
    asm("mul.rn.f32x2 %0,%1,%2;" : "=l"(d) : "l"(a), "l"(b));
    return d;
}
__device__ __forceinline__ float gelu_(float v) {
    return 0.5f * v * (1.f + erff(v * 0.70710678118654752f));
}

// ======================= kernel 1: rmsnorm + QKV =======================
// warp = 4 tokens (2 packed token-pairs). weights in smem rows [e][j] stride 66.
__global__ void __launch_bounds__(256) qkv_kernel(
    const float* __restrict__ x, const float* __restrict__ nw,
    const float* __restrict__ wq, const float* __restrict__ wk,
    const float* __restrict__ wv)
{
    extern __shared__ float sm[];
    float* ws  = sm;                 // 3 * 64*66 = 12672 floats
    float* nws = ws + 3*4224;        // 64
    unsigned long long* htp_all = (unsigned long long*)(nws + 64); // 8 warps * 128 u64

    const int tid = threadIdx.x, lane = tid & 31, w = tid >> 5;

    for (int i = tid; i < 64*64; i += blockDim.x) {
        int e = i >> 6, j = i & 63;
        ws[0*4224 + e*66 + j] = wq[i];
        ws[1*4224 + e*66 + j] = wk[i];
        ws[2*4224 + e*66 + j] = wv[i];
    }
    if (tid < 64) nws[tid] = nw[tid];
    __syncthreads();

    unsigned long long* htp = htp_all + w*128;   // [tp*64 + j]
    float* hview = (float*)htp;

    for (int chunk = blockIdx.x*8 + w; chunk < NT_/4; chunk += gridDim.x*8) {
        const int tok0 = chunk*4;
        // phase A: rmsnorm 4 tokens, write packed token-pairs
        #pragma unroll
        for (int t = 0; t < 4; t++) {
            float xa = x[(tok0+t)*64 + lane];
            float xb = x[(tok0+t)*64 + lane + 32];
            float ss = xa*xa + xb*xb;
            #pragma unroll
            for (int o = 16; o; o >>= 1) ss += __shfl_xor_sync(~0u, ss, o);
            float rinv = rsqrtf(ss * (1.f/64.f) + 1e-5f);
            int tp = t >> 1, c = t & 1;
            hview[(tp*64 + lane)*2 + c]      = xa * rinv * nws[lane];
            hview[(tp*64 + lane + 32)*2 + c] = xb * rinv * nws[lane + 32];
        }
        __syncwarp();

        unsigned long long acc[3][2][2];
        #pragma unroll
        for (int p = 0; p < 3; p++)
            #pragma unroll
            for (int r = 0; r < 2; r++) { acc[p][r][0] = 0ull; acc[p][r][1] = 0ull; }

        #pragma unroll 4
        for (int j = 0; j < 64; j += 2) {
            ulonglong2 h0 = *(const ulonglong2*)(htp + j);
            ulonglong2 h1 = *(const ulonglong2*)(htp + 64 + j);
            #pragma unroll
            for (int p = 0; p < 3; p++)
                #pragma unroll
                for (int r = 0; r < 2; r++) {
                    float2 wf = *(const float2*)(ws + p*4224 + (lane + r*32)*66 + j);
                    unsigned long long wx = pk2(wf.x, wf.x);
                    unsigned long long wy = pk2(wf.y, wf.y);
                    acc[p][r][0] = ffma2_(wx, h0.x, acc[p][r][0]);
                    acc[p][r][0] = ffma2_(wy, h0.y, acc[p][r][0]);
                    acc[p][r][1] = ffma2_(wx, h1.x, acc[p][r][1]);
                    acc[p][r][1] = ffma2_(wy, h1.y, acc[p][r][1]);
                }
        }

        const int b0 = tok0 >> 10, s0 = tok0 & 1023;
        #pragma unroll
        for (int p = 0; p < 3; p++) {
            float* dst = (p == 0) ? g_q : (p == 1 ? g_k : g_v);
            #pragma unroll
            for (int r = 0; r < 2; r++) {
                int e = lane + r*32, hh = e >> 4, d = e & 15;
                float* base = dst + ((b0*H_ + hh)*S_)*HD_ + d;
                #pragma unroll
                for (int tp = 0; tp < 2; tp++) {
                    float2 v = upk2(acc[p][r][tp]);
                    base[(s0 + tp*2    )*HD_] = v.x;
                    base[(s0 + tp*2 + 1)*HD_] = v.y;
                }
            }
        }
        __syncwarp();
    }
}

// ======================= kernel 2: causal attention =======================
// one block per (b,h): 1024 threads, thread = query. K/V streamed in 8 tiles
// of 128 keys into smem (128KB). Inner loop fully f32x2-packed, log2-domain
// online softmax.
__global__ void __launch_bounds__(1024, 1) attn_kernel()
{
    const int bh = blockIdx.x;               // 0..127
    extern __shared__ float sm[];
    float* Ks = sm;                          // 1024*16
    float* Vs = sm + 16384;

    const int q = threadIdx.x;
    const float qs = 0.25f * 1.4426950408889634f;  // 1/sqrt(HD) * log2(e)
    const float* qp = g_q + (bh*S_ + q) * HD_;
    unsigned long long q2[8];
    #pragma unroll
    for (int d = 0; d < 8; d++) q2[d] = pk2(qp[2*d] * qs, qp[2*d+1] * qs);

    float m = -1e30f, l = 0.f;
    unsigned long long acc[8];
    #pragma unroll
    for (int d = 0; d < 8; d++) acc[d] = 0ull;

    const float2* kg = (const float2*)(g_k + bh * S_ * HD_);
    const float2* vg = (const float2*)(g_v + bh * S_ * HD_);
    float2* Ks2 = (float2*)Ks;
    float2* Vs2 = (float2*)Vs;

    #pragma unroll 1
    for (int tile = 0; tile < 8; tile++) {
        int li = tile*1024 + threadIdx.x;
        Ks2[li] = kg[li];
        Vs2[li] = vg[li];
        __syncthreads();

        const int base = tile * 128;
        int jend = q + 1 - base;
        jend = jend < 0 ? 0 : (jend > 128 ? 128 : jend);
        const ulonglong2* kb = (const ulonglong2*)(Ks + base*16);
        const ulonglong2* vb = (const ulonglong2*)(Vs + base*16);

        #pragma unroll 2
        for (int j = 0; j < jend; j++) {
            ulonglong2 k0 = kb[j*4+0], k1 = kb[j*4+1];
            ulonglong2 k2 = kb[j*4+2], k3 = kb[j*4+3];
            unsigned long long ps = fmul2_(q2[0], k0.x);
            ps = ffma2_(q2[1], k0.y, ps);
            ps = ffma2_(q2[2], k1.x, ps);
            ps = ffma2_(q2[3], k1.y, ps);
            ps = ffma2_(q2[4], k2.x, ps);
            ps = ffma2_(q2[5], k2.y, ps);
            ps = ffma2_(q2[6], k3.x, ps);
            ps = ffma2_(q2[7], k3.y, ps);
            float2 sp = upk2(ps);
            float s = sp.x + sp.y;
            if (s > m) {                       // rare after warmup
                float c = exp2f(m - s);
                l *= c;
                unsigned long long c2 = pk2(c, c);
                #pragma unroll
                for (int d = 0; d < 8; d++) acc[d] = fmul2_(acc[d], c2);
                m = s;
            }
            float p = exp2f(s - m);
            l += p;
            unsigned long long p2 = pk2(p, p);
            ulonglong2 v0 = vb[j*4+0], v1 = vb[j*4+1];
            ulonglong2 v2 = vb[j*4+2], v3 = vb[j*4+3];
            acc[0] = ffma2_(p2, v0.x, acc[0]);
            acc[1] = ffma2_(p2, v0.y, acc[1]);
            acc[2] = ffma2_(p2, v1.x, acc[2]);
            acc[3] = ffma2_(p2, v1.y, acc[3]);
            acc[4] = ffma2_(p2, v2.x, acc[4]);
            acc[5] = ffma2_(p2, v2.y, acc[5]);
            acc[6] = ffma2_(p2, v3.x, acc[6]);
            acc[7] = ffma2_(p2, v3.y, acc[7]);
        }
    }

    const float inv = 1.f / l;
    const int b = bh >> 2, h = bh & 3;
    float* op = g_o + (b*S_ + q)*E_ + h*16;
    #pragma unroll
    for (int d = 0; d < 8; d++) {
        float2 a = upk2(acc[d]);
        op[2*d]   = a.x * inv;
        op[2*d+1] = a.y * inv;
    }
}

// ======================= kernel 3: wo-proj + residual + memory read =======================
__global__ void __launch_bounds__(256) mem_kernel(
    const float* __restrict__ x,     const float* __restrict__ mvals,
    const float* __restrict__ maddr, const float* __restrict__ mnw,
    const float* __restrict__ wo,    const float* __restrict__ mq,
    const float* __restrict__ mo,    float* __restrict__ out)
{
    extern __shared__ float sm[];
    float* woT  = sm;              // 64*65
    float* moT  = woT + 4160;      // 64*65
    float* mqT  = moT + 4160;      // 64*33
    float* aT   = mqT + 2112;      // 32*65
    float* mnws = aT + 2080;       // 64
    float* rows = mnws + 64;       // 8 * 96

    const int tid = threadIdx.x, lane = tid & 31, w = tid >> 5;

    for (int i = tid; i < 4096; i += blockDim.x) {
        int e = i >> 6, j = i & 63;
        woT[j*65 + e] = wo[i];
        moT[j*65 + e] = mo[i];
    }
    for (int i = tid; i < AD_*E_; i += blockDim.x) {
        int a = i >> 6, e = i & 63;
        mqT[e*33 + a] = mq[i];
    }
    if (tid < 64) mnws[tid] = mnw[tid];
    if (tid < 64) {
        float ssum = 0.f, v[32];
        #pragma unroll
        for (int a = 0; a < 32; a++) { v[a] = maddr[tid*32 + a]; ssum += v[a]*v[a]; }
        float rn = 1.f / fmaxf(sqrtf(ssum), 1e-12f);
        #pragma unroll
        for (int a = 0; a < 32; a++) aT[a*65 + tid] = v[a] * rn;
    }
    __syncthreads();

    float* hrow = rows + w*96;
    float* qrow = hrow + 64;

    for (int tok = blockIdx.x*8 + w; tok < NT_; tok += gridDim.x*8) {
        const int b = tok >> 10;
        hrow[lane]      = g_o[tok*64 + lane];
        hrow[lane + 32] = g_o[tok*64 + lane + 32];
        __syncwarp();
        float x1a = x[tok*64 + lane], x1b = x[tok*64 + lane + 32];
        {
            float s0 = 0.f, s1 = 0.f;
            #pragma unroll
            for (int j = 0; j < 64; j++) {
                float hv = hrow[j];
                s0 += hv * woT[j*65 + lane];
                s1 += hv * woT[j*65 + lane + 32];
            }
            x1a += s0; x1b += s1;
        }
        __syncwarp();
        float ss = x1a*x1a + x1b*x1b;
        #pragma unroll
        for (int o = 16; o; o >>= 1) ss += __shfl_xor_sync(~0u, ss, o);
        float rinv = rsqrtf(ss * (1.f/64.f) + 1e-5f);
        hrow[lane]      = x1a * rinv * mnws[lane];
        hrow[lane + 32] = x1b * rinv * mnws[lane + 32];
        __syncwarp();
        float qa = 0.f;
        #pragma unroll
        for (int e = 0; e < 64; e++) qa += hrow[e] * mqT[e*33 + lane];
        float qsm = qa*qa;
        #pragma unroll
        for (int o = 16; o; o >>= 1) qsm += __shfl_xor_sync(~0u, qsm, o);
        float rq = 1.f / fmaxf(sqrtf(qsm), 1e-12f);
        qrow[lane] = qa * rq;
        __syncwarp();
        float sc0 = 0.f, sc1 = 0.f;
        #pragma unroll
        for (int a = 0; a < 32; a++) {
            float qv = qrow[a];
            sc0 += qv * aT[a*65 + lane];
            sc1 += qv * aT[a*65 + lane + 32];
        }
        sc0 *= 4.f; sc1 *= 4.f;
        float tv[8]; int ti[8];
        float c0 = sc0, c1 = sc1; int i0 = lane, i1 = lane + 32;
        #pragma unroll
        for (int k = 0; k < 8; k++) {
            float bv; int bidx;
            if (c0 > c1 || (c0 == c1 && i0 < i1)) { bv = c0; bidx = i0; }
            else                                   { bv = c1; bidx = i1; }
            #pragma unroll
            for (int o = 16; o; o >>= 1) {
                float ov = __shfl_xor_sync(~0u, bv, o);
                int   oi = __shfl_xor_sync(~0u, bidx, o);
                if (ov > bv || (ov == bv && oi < bidx)) { bv = ov; bidx = oi; }
            }
            tv[k] = bv; ti[k] = bidx;
            if (bidx == i0) c0 = -1e30f;
            if (bidx == i1) c1 = -1e30f;
        }
        float wsum = 0.f, wk8[8];
        #pragma unroll
        for (int k = 0; k < 8; k++) { wk8[k] = __expf(tv[k] - tv[0]); wsum += wk8[k]; }
        float winv = 1.f / wsum;
        const float* mb = mvals + b * NS_ * E_;
        float r0 = 0.f, r1 = 0.f;
        #pragma unroll
        for (int k = 0; k < 8; k++) {
            float wv = wk8[k] * winv;
            const float* mrow = mb + ti[k]*64;
            r0 += wv * mrow[lane];
            r1 += wv * mrow[lane + 32];
        }
        hrow[lane] = r0; hrow[lane + 32] = r1;
        __syncwarp();
        float o0 = 0.f, o1 = 0.f;
        #pragma unroll
        for (int j = 0; j < 64; j++) {
            float rv = hrow[j];
            o0 += rv * moT[j*65 + lane];
            o1 += rv * moT[j*65 + lane + 32];
        }
        out[tok*64 + lane]      = x1a + o0;
        out[tok*64 + lane + 32] = x1b + o1;
        __syncwarp();
    }
}

// ======================= kernel 4: FFN (in-place on d_out) =======================
// warp = 8 tokens (4 packed token-pairs). Both GEMMs f32x2 token-packed.
__global__ void __launch_bounds__(256, 1) ffn_kernel(
    const float* __restrict__ fnw, const float* __restrict__ w1,
    const float* __restrict__ b1,  const float* __restrict__ w2,
    const float* __restrict__ b2,  float* __restrict__ out)
{
    extern __shared__ float sm[];
    float* w1s = sm;                 // 256*66 = 16896
    float* w2s = w1s + 16896;        // 64*258 = 16512
    float* b1s = w2s + 16512;        // 256
    float* b2s = b1s + 256;          // 64
    float* fns = b2s + 64;           // 64
    unsigned long long* u64base = (unsigned long long*)(fns + 64);
    // per warp: htp 256 u64 (4tp x 64j), hidu 1024 u64 (4tp x 256o)

    const int tid = threadIdx.x, lane = tid & 31, w = tid >> 5;

    for (int i = tid; i < HID_*E_; i += blockDim.x) {
        int o = i >> 6, j = i & 63;
        w1s[o*66 + j] = w1[i];                 // w1[o][j], j contiguous
    }
    for (int i = tid; i < E_*HID_; i += blockDim.x) {
        int e = i >> 8, o = i & 255;
        w2s[e*258 + o] = w2[i];                // w2[e][o], o contiguous
    }
    if (tid < 256) b1s[tid] = b1[tid];
    if (tid < 64) { b2s[tid] = b2[tid]; fns[tid] = fnw[tid]; }
    __syncthreads();

    unsigned long long* htp  = u64base + w*1280;        // 256 u64
    unsigned long long* hidu = htp + 256;               // 1024 u64
    float* hview = (float*)htp;

    for (int chunk = blockIdx.x*8 + w; chunk < NT_/8; chunk += gridDim.x*8) {
        const int tok0 = chunk*8;
        float xr[8][2];
        // phase A: rmsnorm 8 tokens -> packed token-pairs
        #pragma unroll
        for (int t = 0; t < 8; t++) {
            float xa = out[(tok0+t)*64 + lane];
            float xb = out[(tok0+t)*64 + lane + 32];
            xr[t][0] = xa; xr[t][1] = xb;
            float ss = xa*xa + xb*xb;
            #pragma unroll
            for (int o = 16; o; o >>= 1) ss += __shfl_xor_sync(~0u, ss, o);
            float rinv = rsqrtf(ss * (1.f/64.f) + 1e-5f);
            int tp = t >> 1, c = t & 1;
            hview[(tp*64 + lane)*2 + c]      = xa * rinv * fns[lane];
            hview[(tp*64 + lane + 32)*2 + c] = xb * rinv * fns[lane + 32];
        }
        __syncwarp();

        // GEMM1: [8 tok] x [64 -> 256]
        unsigned long long acc[4][8];
        #pragma unroll
        for (int tp = 0; tp < 4; tp++)
            #pragma unroll
            for (int r = 0; r < 8; r++) acc[tp][r] = 0ull;

        #pragma unroll 4
        for (int j = 0; j < 64; j += 2) {
            ulonglong2 hh[4];
            #pragma unroll
            for (int tp = 0; tp < 4; tp++)
                hh[tp] = *(const ulonglong2*)(htp + tp*64 + j);
            #pragma unroll
            for (int r = 0; r < 8; r++) {
                float2 wf = *(const float2*)(w1s + (lane + r*32)*66 + j);
                unsigned long long wx = pk2(wf.x, wf.x);
                unsigned long long wy = pk2(wf.y, wf.y);
                #pragma unroll
                for (int tp = 0; tp < 4; tp++) {
                    acc[tp][r] = ffma2_(wx, hh[tp].x, acc[tp][r]);
                    acc[tp][r] = ffma2_(wy, hh[tp].y, acc[tp][r]);
                }
            }
        }

        // bias + exact GELU -> hidden (token-pair packed)
        #pragma unroll
        for (int r = 0; r < 8; r++) {
            int o = lane + r*32;
            float bb = b1s[o];
            #pragma unroll
            for (int tp = 0; tp < 4; tp++) {
                float2 v = upk2(acc[tp][r]);
                hidu[tp*256 + o] = pk2(gelu_(v.x + bb), gelu_(v.y + bb));
            }
        }
        __syncwarp();

        // GEMM2: [8 tok] x [256 -> 64]
        unsigned long long a2[4][2];
        #pragma unroll
        for (int tp = 0; tp < 4; tp++) { a2[tp][0] = 0ull; a2[tp][1] = 0ull; }

        const float* w2a = w2s + lane*258;
        const float* w2b = w2s + (lane + 32)*258;
        #pragma unroll 4
        for (int o = 0; o < 256; o += 2) {
            float2 wa = *(const float2*)(w2a + o);
            float2 wb = *(const float2*)(w2b + o);
            unsigned long long wax = pk2(wa.x, wa.x), way = pk2(wa.y, wa.y);
            unsigned long long wbx = pk2(wb.x, wb.x), wby = pk2(wb.y, wb.y);
            #pragma unroll
            for (int tp = 0; tp < 4; tp++) {
                ulonglong2 hh = *(const ulonglong2*)(hidu + tp*256 + o);
                a2[tp][0] = ffma2_(wax, hh.x, a2[tp][0]);
                a2[tp][0] = ffma2_(way, hh.y, a2[tp][0]);
                a2[tp][1] = ffma2_(wbx, hh.x, a2[tp][1]);
                a2[tp][1] = ffma2_(wby, hh.y, a2[tp][1]);
            }
        }

        // epilogue: bias + residual
        #pragma unroll
        for (int tp = 0; tp < 4; tp++) {
            float2 v0 = upk2(a2[tp][0]);   // e = lane,    tokens 2tp, 2tp+1
            float2 v1 = upk2(a2[tp][1]);   // e = lane+32
            int t0 = tok0 + 2*tp;
            out[t0*64 + lane]           = xr[2*tp][0]   + b2s[lane]      + v0.x;
            out[(t0+1)*64 + lane]       = xr[2*tp+1][0] + b2s[lane]      + v0.y;
            out[t0*64 + lane + 32]      = xr[2*tp][1]   + b2s[lane + 32] + v1.x;
            out[(t0+1)*64 + lane + 32]  = xr[2*tp+1][1] + b2s[lane + 32] + v1.y;
        }
        __syncwarp();
    }
}

// ======================= launch =======================
extern "C" void kernel_launch(void* const* d_in, const int* in_sizes, int n_in,
                              void* d_out, int out_size)
{
    const float* x     = (const float*)d_in[0];
    const float* maddr = (const float*)d_in[1];
    const float* mvals = (const float*)d_in[2];
    const float* anw   = (const float*)d_in[3];
    const float* wq    = (const float*)d_in[4];
    const float* wk    = (const float*)d_in[5];
    const float* wv    = (const float*)d_in[6];
    const float* wo    = (const float*)d_in[7];
    const float* mnw   = (const float*)d_in[8];
    const float* mq    = (const float*)d_in[9];
    const float* mo    = (const float*)d_in[10];
    const float* fnw   = (const float*)d_in[11];
    const float* w1    = (const float*)d_in[12];
    const float* b1    = (const float*)d_in[13];
    const float* w2    = (const float*)d_in[14];
    const float* b2    = (const float*)d_in[15];
    float* out = (float*)d_out;

    const int QKV_SMEM = (3*4224 + 64) * 4 + 8*128*8;                 // 59,136 B
    const int ATT_SMEM = 32768 * 4;                                   // 131,072 B
    const int MEM_SMEM = (4160*2 + 2112 + 2080 + 64 + 8*96) * 4;      // 53,376 B
    const int FFN_SMEM = (16896 + 16512 + 256 + 64 + 64) * 4 + 8*1280*8; // 216,960 B

    cudaFuncSetAttribute(qkv_kernel, cudaFuncAttributeMaxDynamicSharedMemorySize, QKV_SMEM);
    cudaFuncSetAttribute(attn_kernel, cudaFuncAttributeMaxDynamicSharedMemorySize, ATT_SMEM);
    cudaFuncSetAttribute(mem_kernel, cudaFuncAttributeMaxDynamicSharedMemorySize, MEM_SMEM);
    cudaFuncSetAttribute(ffn_kernel, cudaFuncAttributeMaxDynamicSharedMemorySize, FFN_SMEM);

    qkv_kernel<<<256, 256, QKV_SMEM>>>(x, anw, wq, wk, wv);
    attn_kernel<<<128, 1024, ATT_SMEM>>>();
    mem_kernel<<<512, 256, MEM_SMEM>>>(x, mvals, maddr, mnw, wo, mq, mo, out);
    ffn_kernel<<<128, 256, FFN_SMEM>>>(fnw, w1, b1, w2, b2, out);
}

// round 4
// speedup vs baseline: 1.4708x; 1.0140x over previous
#include <cuda_runtime.h>
#include <cuda_bf16.h>
#include <math.h>

#define B_  32
#define S_  1024
#define E_  64
#define H_  4
#define HD_ 16
#define HID_ 256
#define AD_ 32
#define NS_ 64
#define NT_ (B_*S_)   // 32768 tokens

// ---------------- scratch (no allocations allowed) ----------------
__device__ float g_q[B_*H_*S_*HD_];
__device__ float g_k[B_*H_*S_*HD_];
__device__ float g_v[B_*H_*S_*HD_];
__device__ float g_o[B_*S_*E_];
__device__ unsigned long long g_hid[(NT_/2)*HID_];   // token-pair packed GELU output (32MB)

// ---------------- packed f32x2 helpers ----------------
__device__ __forceinline__ unsigned long long pk2(float lo, float hi) {
    unsigned long long r;
    asm("mov.b64 %0,{%1,%2};" : "=l"(r) : "f"(lo), "f"(hi));
    return r;
}
__device__ __forceinline__ float2 upk2(unsigned long long v) {
    float2 f;
    asm("mov.b64 {%0,%1},%2;" : "=f"(f.x), "=f"(f.y) : "l"(v));
    return f;
}
__device__ __forceinline__ unsigned long long ffma2_(unsigned long long a,
                                                     unsigned long long b,
                                                     unsigned long long c) {
    unsigned long long d;
    asm("fma.rn.f32x2 %0,%1,%2,%3;" : "=l"(d) : "l"(a), "l"(b), "l"(c));
    return d;
}
__device__ __forceinline__ unsigned long long fmul2_(unsigned long long a,
                                                     unsigned long long b) {
    unsigned long long d;
    asm("mul.rn.f32x2 %0,%1,%2;" : "=l"(d) : "l"(a), "l"(b));
    return d;
}
__device__ __forceinline__ float gelu_(float v) {
    return 0.5f * v * (1.f + erff(v * 0.70710678118654752f));
}

// ======================= kernel 1: rmsnorm + QKV =======================
__global__ void __launch_bounds__(256) qkv_kernel(
    const float* __restrict__ x, const float* __restrict__ nw,
    const float* __restrict__ wq, const float* __restrict__ wk,
    const float* __restrict__ wv)
{
    extern __shared__ float sm[];
    float* ws  = sm;                 // 3 * 64*66
    float* nws = ws + 3*4224;        // 64
    unsigned long long* htp_all = (unsigned long long*)(nws + 64); // 8 warps * 128 u64

    const int tid = threadIdx.x, lane = tid & 31, w = tid >> 5;

    for (int i = tid; i < 64*64; i += blockDim.x) {
        int e = i >> 6, j = i & 63;
        ws[0*4224 + e*66 + j] = wq[i];
        ws[1*4224 + e*66 + j] = wk[i];
        ws[2*4224 + e*66 + j] = wv[i];
    }
    if (tid < 64) nws[tid] = nw[tid];
    __syncthreads();

    unsigned long long* htp = htp_all + w*128;   // [tp*64 + j]
    float* hview = (float*)htp;

    for (int chunk = blockIdx.x*8 + w; chunk < NT_/4; chunk += gridDim.x*8) {
        const int tok0 = chunk*4;
        #pragma unroll
        for (int t = 0; t < 4; t++) {
            float xa = x[(tok0+t)*64 + lane];
            float xb = x[(tok0+t)*64 + lane + 32];
            float ss = xa*xa + xb*xb;
            #pragma unroll
            for (int o = 16; o; o >>= 1) ss += __shfl_xor_sync(~0u, ss, o);
            float rinv = rsqrtf(ss * (1.f/64.f) + 1e-5f);
            int tp = t >> 1, c = t & 1;
            hview[(tp*64 + lane)*2 + c]      = xa * rinv * nws[lane];
            hview[(tp*64 + lane + 32)*2 + c] = xb * rinv * nws[lane + 32];
        }
        __syncwarp();

        unsigned long long acc[3][2][2];
        #pragma unroll
        for (int p = 0; p < 3; p++)
            #pragma unroll
            for (int r = 0; r < 2; r++) { acc[p][r][0] = 0ull; acc[p][r][1] = 0ull; }

        #pragma unroll 4
        for (int j = 0; j < 64; j += 2) {
            ulonglong2 h0 = *(const ulonglong2*)(htp + j);
            ulonglong2 h1 = *(const ulonglong2*)(htp + 64 + j);
            #pragma unroll
            for (int p = 0; p < 3; p++)
                #pragma unroll
                for (int r = 0; r < 2; r++) {
                    float2 wf = *(const float2*)(ws + p*4224 + (lane + r*32)*66 + j);
                    unsigned long long wx = pk2(wf.x, wf.x);
                    unsigned long long wy = pk2(wf.y, wf.y);
                    acc[p][r][0] = ffma2_(wx, h0.x, acc[p][r][0]);
                    acc[p][r][0] = ffma2_(wy, h0.y, acc[p][r][0]);
                    acc[p][r][1] = ffma2_(wx, h1.x, acc[p][r][1]);
                    acc[p][r][1] = ffma2_(wy, h1.y, acc[p][r][1]);
                }
        }

        const int b0 = tok0 >> 10, s0 = tok0 & 1023;
        #pragma unroll
        for (int p = 0; p < 3; p++) {
            float* dst = (p == 0) ? g_q : (p == 1 ? g_k : g_v);
            #pragma unroll
            for (int r = 0; r < 2; r++) {
                int e = lane + r*32, hh = e >> 4, d = e & 15;
                float* base = dst + ((b0*H_ + hh)*S_)*HD_ + d;
                #pragma unroll
                for (int tp = 0; tp < 2; tp++) {
                    float2 v = upk2(acc[p][r][tp]);
                    base[(s0 + tp*2    )*HD_] = v.x;
                    base[(s0 + tp*2 + 1)*HD_] = v.y;
                }
            }
        }
        __syncwarp();
    }
}

// ======================= kernel 2: causal attention v2 =======================
// one block per (b,h): 512 threads. Thread t owns queries qa=t and qb=1023-t
// (exactly 1025 key visits per thread -> perfect balance). Full K/V preload.
__global__ void __launch_bounds__(512, 1) attn_kernel()
{
    const int bh = blockIdx.x;               // 0..127
    extern __shared__ float sm[];
    float* Ks = sm;                          // 1024*16
    float* Vs = sm + 16384;

    {   // full preload, coalesced
        const float4* kg4 = (const float4*)(g_k + bh * S_ * HD_);
        const float4* vg4 = (const float4*)(g_v + bh * S_ * HD_);
        float4* Ks4 = (float4*)Ks;
        float4* Vs4 = (float4*)Vs;
        for (int i = threadIdx.x; i < 4096; i += 512) { Ks4[i] = kg4[i]; Vs4[i] = vg4[i]; }
    }
    __syncthreads();

    const int t  = threadIdx.x;              // qa
    const int qb = 1023 - t;
    const float qsc = 0.25f * 1.4426950408889634f;

    unsigned long long q2a[8], q2b[8];
    {
        const float* qpa = g_q + (bh*S_ + t) * HD_;
        const float* qpb = g_q + (bh*S_ + qb) * HD_;
        #pragma unroll
        for (int d = 0; d < 8; d++) {
            q2a[d] = pk2(qpa[2*d] * qsc, qpa[2*d+1] * qsc);
            q2b[d] = pk2(qpb[2*d] * qsc, qpb[2*d+1] * qsc);
        }
    }

    float ma = -1e30f, la = 0.f, mb = -1e30f, lb = 0.f;
    unsigned long long acca[8], accb[8];
    #pragma unroll
    for (int d = 0; d < 8; d++) { acca[d] = 0ull; accb[d] = 0ull; }

    const int tbase     = t & ~31;
    const int loop1_end = tbase + 32;        // j in [0, loop1_end): qb always active
    const int loop2_end = 1024 - tbase;      // j in [loop1_end, loop2_end): qb predicated

    // ---- phase 1: both queries ----
    #pragma unroll 2
    for (int j = 0; j < loop1_end; j++) {
        const ulonglong2* kb = (const ulonglong2*)(Ks + j*16);
        ulonglong2 k0 = kb[0], k1 = kb[1], k2 = kb[2], k3 = kb[3];
        unsigned long long pa = fmul2_(q2a[0], k0.x);
        unsigned long long pb = fmul2_(q2b[0], k0.x);
        pa = ffma2_(q2a[1], k0.y, pa);  pb = ffma2_(q2b[1], k0.y, pb);
        pa = ffma2_(q2a[2], k1.x, pa);  pb = ffma2_(q2b[2], k1.x, pb);
        pa = ffma2_(q2a[3], k1.y, pa);  pb = ffma2_(q2b[3], k1.y, pb);
        pa = ffma2_(q2a[4], k2.x, pa);  pb = ffma2_(q2b[4], k2.x, pb);
        pa = ffma2_(q2a[5], k2.y, pa);  pb = ffma2_(q2b[5], k2.y, pb);
        pa = ffma2_(q2a[6], k3.x, pa);  pb = ffma2_(q2b[6], k3.x, pb);
        pa = ffma2_(q2a[7], k3.y, pa);  pb = ffma2_(q2b[7], k3.y, pb);
        float2 fa = upk2(pa); float sa = fa.x + fa.y;
        float2 fb = upk2(pb); float sb = fb.x + fb.y;

        const ulonglong2* vb4 = (const ulonglong2*)(Vs + j*16);
        ulonglong2 v0 = vb4[0], v1 = vb4[1], v2 = vb4[2], v3 = vb4[3];

        // qb (always active in this phase)
        if (sb > mb) {
            float c = exp2f(mb - sb);
            lb *= c;
            unsigned long long c2 = pk2(c, c);
            #pragma unroll
            for (int d = 0; d < 8; d++) accb[d] = fmul2_(accb[d], c2);
            mb = sb;
        }
        float pbv = exp2f(sb - mb);
        lb += pbv;
        unsigned long long pb2 = pk2(pbv, pbv);
        accb[0] = ffma2_(pb2, v0.x, accb[0]);
        accb[1] = ffma2_(pb2, v0.y, accb[1]);
        accb[2] = ffma2_(pb2, v1.x, accb[2]);
        accb[3] = ffma2_(pb2, v1.y, accb[3]);
        accb[4] = ffma2_(pb2, v2.x, accb[4]);
        accb[5] = ffma2_(pb2, v2.y, accb[5]);
        accb[6] = ffma2_(pb2, v3.x, accb[6]);
        accb[7] = ffma2_(pb2, v3.y, accb[7]);

        // qa (predicated on causal bound)
        if (j <= t) {
            if (sa > ma) {
                float c = exp2f(ma - sa);
                la *= c;
                unsigned long long c2 = pk2(c, c);
                #pragma unroll
                for (int d = 0; d < 8; d++) acca[d] = fmul2_(acca[d], c2);
                ma = sa;
            }
            float pav = exp2f(sa - ma);
            la += pav;
            unsigned long long pa2 = pk2(pav, pav);
            acca[0] = ffma2_(pa2, v0.x, acca[0]);
            acca[1] = ffma2_(pa2, v0.y, acca[1]);
            acca[2] = ffma2_(pa2, v1.x, acca[2]);
            acca[3] = ffma2_(pa2, v1.y, acca[3]);
            acca[4] = ffma2_(pa2, v2.x, acca[4]);
            acca[5] = ffma2_(pa2, v2.y, acca[5]);
            acca[6] = ffma2_(pa2, v3.x, acca[6]);
            acca[7] = ffma2_(pa2, v3.y, acca[7]);
        }
    }

    // ---- phase 2: only qb ----
    #pragma unroll 2
    for (int j = loop1_end; j < loop2_end; j++) {
        const ulonglong2* kb = (const ulonglong2*)(Ks + j*16);
        ulonglong2 k0 = kb[0], k1 = kb[1], k2 = kb[2], k3 = kb[3];
        unsigned long long pb = fmul2_(q2b[0], k0.x);
        pb = ffma2_(q2b[1], k0.y, pb);
        pb = ffma2_(q2b[2], k1.x, pb);
        pb = ffma2_(q2b[3], k1.y, pb);
        pb = ffma2_(q2b[4], k2.x, pb);
        pb = ffma2_(q2b[5], k2.y, pb);
        pb = ffma2_(q2b[6], k3.x, pb);
        pb = ffma2_(q2b[7], k3.y, pb);
        float2 fb = upk2(pb); float sb = fb.x + fb.y;

        if (j <= qb) {
            const ulonglong2* vb4 = (const ulonglong2*)(Vs + j*16);
            ulonglong2 v0 = vb4[0], v1 = vb4[1], v2 = vb4[2], v3 = vb4[3];
            if (sb > mb) {
                float c = exp2f(mb - sb);
                lb *= c;
                unsigned long long c2 = pk2(c, c);
                #pragma unroll
                for (int d = 0; d < 8; d++) accb[d] = fmul2_(accb[d], c2);
                mb = sb;
            }
            float pbv = exp2f(sb - mb);
            lb += pbv;
            unsigned long long pb2 = pk2(pbv, pbv);
            accb[0] = ffma2_(pb2, v0.x, accb[0]);
            accb[1] = ffma2_(pb2, v0.y, accb[1]);
            accb[2] = ffma2_(pb2, v1.x, accb[2]);
            accb[3] = ffma2_(pb2, v1.y, accb[3]);
            accb[4] = ffma2_(pb2, v2.x, accb[4]);
            accb[5] = ffma2_(pb2, v2.y, accb[5]);
            accb[6] = ffma2_(pb2, v3.x, accb[6]);
            accb[7] = ffma2_(pb2, v3.y, accb[7]);
        }
    }

    const int b = bh >> 2, h = bh & 3;
    {
        float inv = 1.f / la;
        float* op = g_o + (b*S_ + t)*E_ + h*16;
        #pragma unroll
        for (int d = 0; d < 8; d++) {
            float2 a = upk2(acca[d]);
            op[2*d]   = a.x * inv;
            op[2*d+1] = a.y * inv;
        }
    }
    {
        float inv = 1.f / lb;
        float* op = g_o + (b*S_ + qb)*E_ + h*16;
        #pragma unroll
        for (int d = 0; d < 8; d++) {
            float2 a = upk2(accb[d]);
            op[2*d]   = a.x * inv;
            op[2*d+1] = a.y * inv;
        }
    }
}

// ======================= kernel 3: wo-proj + residual + memory read =======================
__global__ void __launch_bounds__(256) mem_kernel(
    const float* __restrict__ x,     const float* __restrict__ mvals,
    const float* __restrict__ maddr, const float* __restrict__ mnw,
    const float* __restrict__ wo,    const float* __restrict__ mq,
    const float* __restrict__ mo,    float* __restrict__ out)
{
    extern __shared__ float sm[];
    float* woT  = sm;              // 64*65
    float* moT  = woT + 4160;      // 64*65
    float* mqT  = moT + 4160;      // 64*33
    float* aT   = mqT + 2112;      // 32*65
    float* mnws = aT + 2080;       // 64
    float* rows = mnws + 64;       // 8 * 96

    const int tid = threadIdx.x, lane = tid & 31, w = tid >> 5;

    for (int i = tid; i < 4096; i += blockDim.x) {
        int e = i >> 6, j = i & 63;
        woT[j*65 + e] = wo[i];
        moT[j*65 + e] = mo[i];
    }
    for (int i = tid; i < AD_*E_; i += blockDim.x) {
        int a = i >> 6, e = i & 63;
        mqT[e*33 + a] = mq[i];
    }
    if (tid < 64) mnws[tid] = mnw[tid];
    if (tid < 64) {
        float ssum = 0.f, v[32];
        #pragma unroll
        for (int a = 0; a < 32; a++) { v[a] = maddr[tid*32 + a]; ssum += v[a]*v[a]; }
        float rn = 1.f / fmaxf(sqrtf(ssum), 1e-12f);
        #pragma unroll
        for (int a = 0; a < 32; a++) aT[a*65 + tid] = v[a] * rn;
    }
    __syncthreads();

    float* hrow = rows + w*96;
    float* qrow = hrow + 64;

    for (int tok = blockIdx.x*8 + w; tok < NT_; tok += gridDim.x*8) {
        const int b = tok >> 10;
        hrow[lane]      = g_o[tok*64 + lane];
        hrow[lane + 32] = g_o[tok*64 + lane + 32];
        __syncwarp();
        float x1a = x[tok*64 + lane], x1b = x[tok*64 + lane + 32];
        {
            float s0 = 0.f, s1 = 0.f;
            #pragma unroll
            for (int j = 0; j < 64; j++) {
                float hv = hrow[j];
                s0 += hv * woT[j*65 + lane];
                s1 += hv * woT[j*65 + lane + 32];
            }
            x1a += s0; x1b += s1;
        }
        __syncwarp();
        float ss = x1a*x1a + x1b*x1b;
        #pragma unroll
        for (int o = 16; o; o >>= 1) ss += __shfl_xor_sync(~0u, ss, o);
        float rinv = rsqrtf(ss * (1.f/64.f) + 1e-5f);
        hrow[lane]      = x1a * rinv * mnws[lane];
        hrow[lane + 32] = x1b * rinv * mnws[lane + 32];
        __syncwarp();
        float qa = 0.f;
        #pragma unroll
        for (int e = 0; e < 64; e++) qa += hrow[e] * mqT[e*33 + lane];
        float qsm = qa*qa;
        #pragma unroll
        for (int o = 16; o; o >>= 1) qsm += __shfl_xor_sync(~0u, qsm, o);
        float rq = 1.f / fmaxf(sqrtf(qsm), 1e-12f);
        qrow[lane] = qa * rq;
        __syncwarp();
        float sc0 = 0.f, sc1 = 0.f;
        #pragma unroll
        for (int a = 0; a < 32; a++) {
            float qv = qrow[a];
            sc0 += qv * aT[a*65 + lane];
            sc1 += qv * aT[a*65 + lane + 32];
        }
        sc0 *= 4.f; sc1 *= 4.f;
        float tv[8]; int ti[8];
        float c0 = sc0, c1 = sc1; int i0 = lane, i1 = lane + 32;
        #pragma unroll
        for (int k = 0; k < 8; k++) {
            float bv; int bidx;
            if (c0 > c1 || (c0 == c1 && i0 < i1)) { bv = c0; bidx = i0; }
            else                                   { bv = c1; bidx = i1; }
            #pragma unroll
            for (int o = 16; o; o >>= 1) {
                float ov = __shfl_xor_sync(~0u, bv, o);
                int   oi = __shfl_xor_sync(~0u, bidx, o);
                if (ov > bv || (ov == bv && oi < bidx)) { bv = ov; bidx = oi; }
            }
            tv[k] = bv; ti[k] = bidx;
            if (bidx == i0) c0 = -1e30f;
            if (bidx == i1) c1 = -1e30f;
        }
        float wsum = 0.f, wk8[8];
        #pragma unroll
        for (int k = 0; k < 8; k++) { wk8[k] = __expf(tv[k] - tv[0]); wsum += wk8[k]; }
        float winv = 1.f / wsum;
        const float* mb = mvals + b * NS_ * E_;
        float r0 = 0.f, r1 = 0.f;
        #pragma unroll
        for (int k = 0; k < 8; k++) {
            float wv = wk8[k] * winv;
            const float* mrow = mb + ti[k]*64;
            r0 += wv * mrow[lane];
            r1 += wv * mrow[lane + 32];
        }
        hrow[lane] = r0; hrow[lane + 32] = r1;
        __syncwarp();
        float o0 = 0.f, o1 = 0.f;
        #pragma unroll
        for (int j = 0; j < 64; j++) {
            float rv = hrow[j];
            o0 += rv * moT[j*65 + lane];
            o1 += rv * moT[j*65 + lane + 32];
        }
        out[tok*64 + lane]      = x1a + o0;
        out[tok*64 + lane + 32] = x1b + o1;
        __syncwarp();
    }
}

// ======================= kernel 4a: FFN GEMM1 + GELU -> g_hid =======================
// warp = 8 tokens (4 packed token-pairs). Small smem -> 2 blocks/SM.
__global__ void __launch_bounds__(256) ffn1_kernel(
    const float* __restrict__ fnw, const float* __restrict__ w1,
    const float* __restrict__ b1,  const float* __restrict__ out)
{
    extern __shared__ float sm[];
    float* w1s = sm;                 // 256*66 = 16896
    float* b1s = w1s + 16896;        // 256
    float* fns = b1s + 256;          // 64
    unsigned long long* u64base = (unsigned long long*)(fns + 64);  // 8 warps * 256 u64

    const int tid = threadIdx.x, lane = tid & 31, w = tid >> 5;

    for (int i = tid; i < HID_*E_; i += blockDim.x) {
        int o = i >> 6, j = i & 63;
        w1s[o*66 + j] = w1[i];
    }
    if (tid < 256) b1s[tid] = b1[tid];
    if (tid < 64) fns[tid] = fnw[tid];
    __syncthreads();

    unsigned long long* htp = u64base + w*256;
    float* hview = (float*)htp;

    for (int chunk = blockIdx.x*8 + w; chunk < NT_/8; chunk += gridDim.x*8) {
        const int tok0 = chunk*8;
        #pragma unroll
        for (int t = 0; t < 8; t++) {
            float xa = out[(tok0+t)*64 + lane];
            float xb = out[(tok0+t)*64 + lane + 32];
            float ss = xa*xa + xb*xb;
            #pragma unroll
            for (int o = 16; o; o >>= 1) ss += __shfl_xor_sync(~0u, ss, o);
            float rinv = rsqrtf(ss * (1.f/64.f) + 1e-5f);
            int tp = t >> 1, c = t & 1;
            hview[(tp*64 + lane)*2 + c]      = xa * rinv * fns[lane];
            hview[(tp*64 + lane + 32)*2 + c] = xb * rinv * fns[lane + 32];
        }
        __syncwarp();

        unsigned long long acc[4][8];
        #pragma unroll
        for (int tp = 0; tp < 4; tp++)
            #pragma unroll
            for (int r = 0; r < 8; r++) acc[tp][r] = 0ull;

        #pragma unroll 4
        for (int j = 0; j < 64; j += 2) {
            ulonglong2 hh[4];
            #pragma unroll
            for (int tp = 0; tp < 4; tp++)
                hh[tp] = *(const ulonglong2*)(htp + tp*64 + j);
            #pragma unroll
            for (int r = 0; r < 8; r++) {
                float2 wf = *(const float2*)(w1s + (lane + r*32)*66 + j);
                unsigned long long wx = pk2(wf.x, wf.x);
                unsigned long long wy = pk2(wf.y, wf.y);
                #pragma unroll
                for (int tp = 0; tp < 4; tp++) {
                    acc[tp][r] = ffma2_(wx, hh[tp].x, acc[tp][r]);
                    acc[tp][r] = ffma2_(wy, hh[tp].y, acc[tp][r]);
                }
            }
        }

        // bias + exact GELU -> g_hid (token-pair packed, coalesced)
        unsigned long long* gh = g_hid + (tok0 >> 1) * HID_;
        #pragma unroll
        for (int r = 0; r < 8; r++) {
            int o = lane + r*32;
            float bb = b1s[o];
            #pragma unroll
            for (int tp = 0; tp < 4; tp++) {
                float2 v = upk2(acc[tp][r]);
                gh[tp*256 + o] = pk2(gelu_(v.x + bb), gelu_(v.y + bb));
            }
        }
        __syncwarp();
    }
}

// ======================= kernel 4b: FFN GEMM2 + residual =======================
__global__ void __launch_bounds__(256) ffn2_kernel(
    const float* __restrict__ w2, const float* __restrict__ b2,
    float* __restrict__ out)
{
    extern __shared__ float sm[];
    float* w2s = sm;                 // 64*258 = 16512
    float* b2s = w2s + 16512;        // 64

    const int tid = threadIdx.x, lane = tid & 31, w = tid >> 5;

    for (int i = tid; i < E_*HID_; i += blockDim.x) {
        int e = i >> 8, o = i & 255;
        w2s[e*258 + o] = w2[i];
    }
    if (tid < 64) b2s[tid] = b2[tid];
    __syncthreads();

    const float* w2a = w2s + lane*258;
    const float* w2b = w2s + (lane + 32)*258;

    for (int chunk = blockIdx.x*8 + w; chunk < NT_/8; chunk += gridDim.x*8) {
        const int tok0 = chunk*8;
        const unsigned long long* gh = g_hid + (tok0 >> 1) * HID_;

        unsigned long long a2[4][2];
        #pragma unroll
        for (int tp = 0; tp < 4; tp++) { a2[tp][0] = 0ull; a2[tp][1] = 0ull; }

        #pragma unroll 4
        for (int o = 0; o < 256; o += 2) {
            float2 wa = *(const float2*)(w2a + o);
            float2 wb = *(const float2*)(w2b + o);
            unsigned long long wax = pk2(wa.x, wa.x), way = pk2(wa.y, wa.y);
            unsigned long long wbx = pk2(wb.x, wb.x), wby = pk2(wb.y, wb.y);
            #pragma unroll
            for (int tp = 0; tp < 4; tp++) {
                ulonglong2 hh = *(const ulonglong2*)(gh + tp*256 + o);
                a2[tp][0] = ffma2_(wax, hh.x, a2[tp][0]);
                a2[tp][0] = ffma2_(way, hh.y, a2[tp][0]);
                a2[tp][1] = ffma2_(wbx, hh.x, a2[tp][1]);
                a2[tp][1] = ffma2_(wby, hh.y, a2[tp][1]);
            }
        }

        #pragma unroll
        for (int tp = 0; tp < 4; tp++) {
            float2 v0 = upk2(a2[tp][0]);
            float2 v1 = upk2(a2[tp][1]);
            int t0 = tok0 + 2*tp;
            out[t0*64 + lane]          += b2s[lane]      + v0.x;
            out[(t0+1)*64 + lane]      += b2s[lane]      + v0.y;
            out[t0*64 + lane + 32]     += b2s[lane + 32] + v1.x;
            out[(t0+1)*64 + lane + 32] += b2s[lane + 32] + v1.y;
        }
    }
}

// ======================= launch =======================
extern "C" void kernel_launch(void* const* d_in, const int* in_sizes, int n_in,
                              void* d_out, int out_size)
{
    const float* x     = (const float*)d_in[0];
    const float* maddr = (const float*)d_in[1];
    const float* mvals = (const float*)d_in[2];
    const float* anw   = (const float*)d_in[3];
    const float* wq    = (const float*)d_in[4];
    const float* wk    = (const float*)d_in[5];
    const float* wv    = (const float*)d_in[6];
    const float* wo    = (const float*)d_in[7];
    const float* mnw   = (const float*)d_in[8];
    const float* mq    = (const float*)d_in[9];
    const float* mo    = (const float*)d_in[10];
    const float* fnw   = (const float*)d_in[11];
    const float* w1    = (const float*)d_in[12];
    const float* b1    = (const float*)d_in[13];
    const float* w2    = (const float*)d_in[14];
    const float* b2    = (const float*)d_in[15];
    float* out = (float*)d_out;

    const int QKV_SMEM  = (3*4224 + 64) * 4 + 8*128*8;   // 59,136 B
    const int ATT_SMEM  = 32768 * 4;                     // 131,072 B
    const int MEM_SMEM  = (4160*2 + 2112 + 2080 + 64 + 8*96) * 4;  // 53,376 B
    const int FFN1_SMEM = (16896 + 256 + 64) * 4 + 8*256*8;        // 85,248 B
    const int FFN2_SMEM = (16512 + 64) * 4;                        // 66,304 B

    cudaFuncSetAttribute(qkv_kernel, cudaFuncAttributeMaxDynamicSharedMemorySize, QKV_SMEM);
    cudaFuncSetAttribute(attn_kernel, cudaFuncAttributeMaxDynamicSharedMemorySize, ATT_SMEM);
    cudaFuncSetAttribute(mem_kernel, cudaFuncAttributeMaxDynamicSharedMemorySize, MEM_SMEM);
    cudaFuncSetAttribute(ffn1_kernel, cudaFuncAttributeMaxDynamicSharedMemorySize, FFN1_SMEM);
    cudaFuncSetAttribute(ffn2_kernel, cudaFuncAttributeMaxDynamicSharedMemorySize, FFN2_SMEM);

    qkv_kernel<<<296, 256, QKV_SMEM>>>(x, anw, wq, wk, wv);
    attn_kernel<<<128, 512, ATT_SMEM>>>();
    mem_kernel<<<592, 256, MEM_SMEM>>>(x, mvals, maddr, mnw, wo, mq, mo, out);
    ffn1_kernel<<<296, 256, FFN1_SMEM>>>(fnw, w1, b1, out);
    ffn2_kernel<<<296, 256, FFN2_SMEM>>>(w2, b2, out);
}